// round 1
// baseline (speedup 1.0000x reference)
#include <cuda_runtime.h>

// Deformable Conv3d, fp32.
// Stage 1 (prep): transpose x -> channels-last xT[b][spatial][c];
//                 weight -> wT[k][c][o].
// Stage 2 (fused): per block: 32 output points, all 64 output channels.
//   Loop k in 0..26:
//     - each warp owns 4 points; lanes gather trilinear corners from xT
//       (coalesced 256B channel vectors), reduce across half-warps,
//       write s[p][c] to shared.
//     - stage wT[k] (64x64) to shared.
//     - small GEMM: acc[p][o] += sW[c][o] * s[p][c].
//   Epilogue: + bias, store.

namespace {
constexpr int B_    = 2;
constexpr int CIN_  = 64;
constexpr int COUT_ = 64;
constexpr int D_    = 8;
constexpr int H_    = 32;
constexpr int W_    = 32;
constexpr int K_    = 27;
constexpr int P_    = D_ * H_ * W_;   // 8192 points per batch
constexpr int TP    = 32;             // points per block
constexpr int THREADS = 256;
}

// scratch (no cudaMalloc allowed)
__device__ float g_xT[B_ * P_ * CIN_];       // [b][spatial][c]  4 MB
__device__ float g_wT[K_ * CIN_ * COUT_];    // [k][c][o]        432 KB

__global__ void prep_kernel(const float* __restrict__ x,
                            const float* __restrict__ w) {
    int stride = gridDim.x * blockDim.x;
    int tid = blockIdx.x * blockDim.x + threadIdx.x;
    // x: [b][c][spatial] -> xT: [b][spatial][c]
    for (int i = tid; i < B_ * CIN_ * P_; i += stride) {
        int s = i % P_;
        int c = (i / P_) % CIN_;
        int b = i / (P_ * CIN_);
        g_xT[(b * P_ + s) * CIN_ + c] = x[i];
    }
    // w: [o][c][k] -> wT: [k][c][o]
    for (int i = tid; i < COUT_ * CIN_ * K_; i += stride) {
        int k = i % K_;
        int c = (i / K_) % CIN_;
        int o = i / (K_ * CIN_);
        g_wT[(k * CIN_ + c) * COUT_ + o] = w[i];
    }
}

__global__ __launch_bounds__(THREADS)
void deform_kernel(const float* __restrict__ offset,
                   const float* __restrict__ bias,
                   float* __restrict__ out) {
    __shared__ float sS[TP][CIN_ + 4];   // [p][c], row = 68 floats (272B, 16B-aligned)
    __shared__ float sW[CIN_ * COUT_];   // [c][o]

    const int tid  = threadIdx.x;
    const int lane = tid & 31;
    const int warp = tid >> 5;           // 8 warps
    const int blk  = blockIdx.x;         // 512 blocks
    const int b    = blk >> 8;           // 256 blocks per batch
    const int p0   = (blk & 255) * TP;

    const float* offB = offset + (size_t)b * 3 * K_ * P_;
    const float* xTb  = g_xT   + (size_t)b * P_ * CIN_;

    const int pl_base = warp * 4;        // this warp's 4 local points

    int od[4], oh[4], ow[4], pg[4];
#pragma unroll
    for (int i = 0; i < 4; i++) {
        int p = p0 + pl_base + i;
        pg[i] = p;
        od[i] = p >> 10;                 // / (32*32)
        oh[i] = (p >> 5) & 31;
        ow[i] = p & 31;
    }

    float acc[4][2];
#pragma unroll
    for (int i = 0; i < 4; i++) { acc[i][0] = 0.f; acc[i][1] = 0.f; }

    const int half = lane >> 4;          // 0: even corners, 1: odd corners
    const int c4   = lane & 15;          // float4 channel chunk

    for (int k = 0; k < K_; k++) {
        // stage wT[k] -> shared (4096 floats, float4)
        {
            const float4* wsrc = reinterpret_cast<const float4*>(g_wT + k * CIN_ * COUT_);
            float4* wdst = reinterpret_cast<float4*>(sW);
            for (int i = tid; i < (CIN_ * COUT_) / 4; i += THREADS)
                wdst[i] = wsrc[i];
        }

        const int kd = k / 9, kh = (k / 3) % 3, kw = k % 3;

        // ---- sampling: warp fills sS rows pl_base..pl_base+3 ----
#pragma unroll
        for (int i = 0; i < 4; i++) {
            const int p = pg[i];
            float zd = (float)(od[i] - 1 + kd) + __ldg(&offB[(3 * k + 0) * P_ + p]);
            float zh = (float)(oh[i] - 1 + kh) + __ldg(&offB[(3 * k + 1) * P_ + p]);
            float zw = (float)(ow[i] - 1 + kw) + __ldg(&offB[(3 * k + 2) * P_ + p]);
            float fd = floorf(zd), fh = floorf(zh), fw = floorf(zw);
            int d0 = (int)fd, h0 = (int)fh, w0 = (int)fw;
            float rd = zd - fd, rh = zh - fh, rw = zw - fw;

            float4 a = make_float4(0.f, 0.f, 0.f, 0.f);
#pragma unroll
            for (int jj = 0; jj < 4; jj++) {
                int j  = jj * 2 + half;
                int dd = (j >> 2) & 1, dh = (j >> 1) & 1, dw = j & 1;
                int di = d0 + dd, hi = h0 + dh, wi = w0 + dw;
                bool valid = (di >= 0) & (di < D_) & (hi >= 0) & (hi < H_) &
                             (wi >= 0) & (wi < W_);
                float wgt = (dd ? rd : 1.f - rd) * (dh ? rh : 1.f - rh) *
                            (dw ? rw : 1.f - rw);
                wgt = valid ? wgt : 0.f;
                int dic = min(max(di, 0), D_ - 1);
                int hic = min(max(hi, 0), H_ - 1);
                int wic = min(max(wi, 0), W_ - 1);
                int idx = (dic * H_ + hic) * W_ + wic;
                // lanes 0..15 / 16..31 each read a contiguous 256B channel vector
                float4 v = *reinterpret_cast<const float4*>(xTb + idx * CIN_ + c4 * 4);
                a.x += wgt * v.x; a.y += wgt * v.y;
                a.z += wgt * v.z; a.w += wgt * v.w;
            }
            // combine the two corner-halves of the warp
            a.x += __shfl_down_sync(0xffffffffu, a.x, 16);
            a.y += __shfl_down_sync(0xffffffffu, a.y, 16);
            a.z += __shfl_down_sync(0xffffffffu, a.z, 16);
            a.w += __shfl_down_sync(0xffffffffu, a.w, 16);
            if (half == 0)
                *reinterpret_cast<float4*>(&sS[pl_base + i][c4 * 4]) = a;
        }
        __syncthreads();

        // ---- GEMM: 64 c x (2 o per lane) x 4 points ----
#pragma unroll 16
        for (int c = 0; c < CIN_; c++) {
            float w0 = sW[c * COUT_ + lane];        // conflict-free
            float w1 = sW[c * COUT_ + lane + 32];
#pragma unroll
            for (int i = 0; i < 4; i++) {
                float s = sS[pl_base + i][c];       // warp-uniform broadcast
                acc[i][0] += w0 * s;
                acc[i][1] += w1 * s;
            }
        }
        __syncthreads();
    }

    const float b0 = bias[lane], b1 = bias[lane + 32];
#pragma unroll
    for (int i = 0; i < 4; i++) {
        int p = pg[i];
        out[((size_t)b * COUT_ + lane) * P_ + p]      = acc[i][0] + b0;
        out[((size_t)b * COUT_ + lane + 32) * P_ + p] = acc[i][1] + b1;
    }
}

extern "C" void kernel_launch(void* const* d_in, const int* in_sizes, int n_in,
                              void* d_out, int out_size) {
    const float* x      = (const float*)d_in[0];
    const float* offset = (const float*)d_in[1];
    const float* weight = (const float*)d_in[2];
    const float* bias   = (const float*)d_in[3];
    float* out = (float*)d_out;

    prep_kernel<<<256, THREADS>>>(x, weight);
    deform_kernel<<<B_ * (P_ / TP), THREADS>>>(offset, bias, out);
}